// round 7
// baseline (speedup 1.0000x reference)
#include <cuda_runtime.h>
#include <cstdint>
#include <math.h>

// Problem constants
#define HN    1024
#define EMBD  512
#define VOC   32000
#define BB    16
#define SEQ   128
#define MROWS (BB*SEQ)   // 2048
#define G4    (4*HN)     // 4096

// Scratch (device globals: allocation-free)
__device__ float    g_XG[MROWS * G4];            // [2048,4096] fp32 gate projections
__device__ unsigned g_HS[MROWS * HN];            // [2048,1024] hidden states (tf32 bits)
__device__ unsigned g_Arows[MROWS * EMBD];       // gathered emb rows as tf32 bits
__device__ unsigned g_Wih_t[G4 * EMBD];          // W_ih as tf32 bits
__device__ unsigned g_Wfc_t[(size_t)VOC * HN];   // W_fc as tf32 bits
__device__ unsigned g_Hb[2][BB * HN];            // h double buffer (tf32 bits)
__device__ float    g_C[BB * HN];
__device__ unsigned g_flags[128];                // per-CTA barrier flags

__device__ __forceinline__ unsigned f2tf(float x){
    unsigned u; asm("cvt.rna.tf32.f32 %0, %1;" : "=r"(u) : "f"(x)); return u;
}

#define MMA_TF32(d, a0,a1,a2,a3, b0,b1) \
  asm volatile("mma.sync.aligned.m16n8k8.row.col.f32.tf32.tf32.f32 " \
    "{%0,%1,%2,%3}, {%4,%5,%6,%7}, {%8,%9}, {%0,%1,%2,%3};\n" \
    : "+f"(d[0]), "+f"(d[1]), "+f"(d[2]), "+f"(d[3]) \
    : "r"(a0), "r"(a1), "r"(a2), "r"(a3), "r"(b0), "r"(b1))

#define CP16(dst,src) asm volatile("cp.async.cg.shared.global [%0], [%1], 16;\n" :: "r"(dst), "l"(src))
#define CP_COMMIT()   asm volatile("cp.async.commit_group;\n")
#define CP_WAIT(n)    asm volatile("cp.async.wait_group %0;\n" :: "n"(n))

// ============================================================================
// fp32 -> tf32-bits conversion (grid-stride, float4)
// ============================================================================
__global__ void __launch_bounds__(256) cvt_tf32_kernel(
    const float4* __restrict__ in, uint4* __restrict__ out, int n4)
{
    int i = blockIdx.x * blockDim.x + threadIdx.x;
    int stride = gridDim.x * blockDim.x;
    for (; i < n4; i += stride){
        float4 v = in[i];
        uint4 u; u.x=f2tf(v.x); u.y=f2tf(v.y); u.z=f2tf(v.z); u.w=f2tf(v.w);
        out[i] = u;
    }
}

// Gather-convert embedding rows: out[r] = tf32(emb[tgt[r]])
__global__ void __launch_bounds__(128) gather_cvt_kernel(
    const float* __restrict__ emb, const int* __restrict__ tgt,
    unsigned* __restrict__ out)
{
    int row = blockIdx.x;
    const float4* src = (const float4*)(emb + (size_t)tgt[row] * EMBD);
    uint4* dst = (uint4*)(out + (size_t)row * EMBD);
    int t = threadIdx.x;
    float4 v = src[t];
    uint4 u; u.x=f2tf(v.x); u.y=f2tf(v.y); u.z=f2tf(v.z); u.w=f2tf(v.w);
    dst[t] = u;
}

// ============================================================================
// TF32 GEMM on tf32-bit operands: C[M,N] = A[M,K] @ B[N,K]^T + bias0 (+bias1)
// BM=128, BN=128, BK=32, 256 threads, 3-stage cp.async pipeline.
// Fragment loads are LDS.128: thread t4 consumes smem k-quads [t4*8 .. t4*8+7];
// the k-reduction is order-invariant and A/B agree on the permutation, so no
// data layout change is needed anywhere.
// Grid: x = M tiles (fast), y = N tiles  => consecutive CTAs share the B tile.
// ============================================================================
__global__ void __launch_bounds__(256) gemm_tf32(
    const unsigned* __restrict__ A, const unsigned* __restrict__ B,
    const float* __restrict__ bias0, const float* __restrict__ bias1,
    float* __restrict__ C, int M, int N, int K)
{
    constexpr int BM=128, BN=128, BK=32, LD=36, STG=3;
    extern __shared__ unsigned smem[];
    unsigned* As = smem;                   // [3][128][36]
    unsigned* Bs = smem + STG*BM*LD;       // [3][128][36]

    const int tid  = threadIdx.x;
    const int lane = tid & 31, w = tid >> 5;
    const int bm0  = blockIdx.x * BM;
    const int bn0  = blockIdx.y * BN;
    const int mb   = (w & 3) * 32;
    const int nb   = (w >> 2) * 64;
    const int g    = lane >> 2, t4 = lane & 3;

    const unsigned* asrc[4]; unsigned adst[4];
    const unsigned* bsrc[4]; unsigned bdst[4];
    unsigned As_b = (unsigned)__cvta_generic_to_shared(As);
    unsigned Bs_b = (unsigned)__cvta_generic_to_shared(Bs);
    #pragma unroll
    for (int j=0;j<4;j++){
        int idx = tid + 256*j;
        int r = idx >> 3, c4 = idx & 7;
        asrc[j] = A + (size_t)(bm0 + r) * K + c4*4;
        adst[j] = As_b + (unsigned)((r*LD + c4*4) * 4);
        bsrc[j] = B + (size_t)(bn0 + r) * K + c4*4;
        bdst[j] = Bs_b + (unsigned)((r*LD + c4*4) * 4);
    }
    const unsigned stS = BM*LD*4;

    float acc[2][8][4];
    #pragma unroll
    for (int i=0;i<2;i++)
        #pragma unroll
        for (int j=0;j<8;j++)
            #pragma unroll
            for (int k=0;k<4;k++) acc[i][j][k]=0.f;

    const int niter = K / BK;
    // prologue: stages 0..2
    #pragma unroll
    for (int st=0; st<STG; st++){
        #pragma unroll
        for (int j=0;j<4;j++){
            CP16(adst[j]+st*stS, asrc[j]+st*BK);
            CP16(bdst[j]+st*stS, bsrc[j]+st*BK);
        }
        CP_COMMIT();
    }

    for (int it=0; it<niter; it++){
        if (it < niter-2)       { CP_WAIT(2); }
        else if (it == niter-2) { CP_WAIT(1); }
        else                    { CP_WAIT(0); }
        __syncthreads();

        const int s = it % STG;
        const unsigned* As_ = As + s*BM*LD;
        const unsigned* Bs_ = Bs + s*BM*LD;
        #pragma unroll
        for (int kkp=0; kkp<2; kkp++){
            uint4 af[2][2], bf[8];
            #pragma unroll
            for (int mt=0; mt<2; mt++){
                const unsigned* p = As_ + (mb + mt*16 + g)*LD + t4*8 + kkp*4;
                af[mt][0] = *(const uint4*)p;
                af[mt][1] = *(const uint4*)(p + 8*LD);
            }
            #pragma unroll
            for (int nt=0; nt<8; nt++)
                bf[nt] = *(const uint4*)(Bs_ + (nb + nt*8 + g)*LD + t4*8 + kkp*4);
            #pragma unroll
            for (int mt=0; mt<2; mt++)
                #pragma unroll
                for (int nt=0; nt<8; nt++){
                    MMA_TF32(acc[mt][nt], af[mt][0].x, af[mt][1].x, af[mt][0].y, af[mt][1].y,
                             bf[nt].x, bf[nt].y);
                    MMA_TF32(acc[mt][nt], af[mt][0].z, af[mt][1].z, af[mt][0].w, af[mt][1].w,
                             bf[nt].z, bf[nt].w);
                }
        }
        __syncthreads();
        if (it + STG < niter){
            const int k0 = (it + STG) * BK;
            const unsigned so = (unsigned)s * stS;
            #pragma unroll
            for (int j=0;j<4;j++){ CP16(adst[j]+so, asrc[j]+k0); CP16(bdst[j]+so, bsrc[j]+k0); }
            CP_COMMIT();
        }
    }

    #pragma unroll
    for (int mt=0; mt<2; mt++){
        int row = bm0 + mb + mt*16 + g;
        #pragma unroll
        for (int nt=0; nt<8; nt++){
            int col = bn0 + nb + nt*8 + 2*t4;
            float b0v = bias0[col], b1v = bias0[col+1];
            if (bias1){ b0v += bias1[col]; b1v += bias1[col+1]; }
            float2 v0 = make_float2(acc[mt][nt][0] + b0v, acc[mt][nt][1] + b1v);
            float2 v1 = make_float2(acc[mt][nt][2] + b0v, acc[mt][nt][3] + b1v);
            *(float2*)(C + (size_t)row*N + col)     = v0;
            *(float2*)(C + (size_t)(row+8)*N + col) = v1;
        }
    }
}

// ============================================================================
// Persistent LSTM recurrence: 128 CTAs (1/SM), each owns 8 hidden units.
// Flag-array release/acquire grid barrier (no serialized atomics).
// h double-buffered in tf32 bits (race-free, no per-step cvt).
// Vectorized LDS.128 fragment loads via the same free k-permutation.
// ============================================================================
__global__ void __launch_bounds__(256) lstm_kernel(const float* __restrict__ W_hh)
{
    constexpr int LDW = HN + 4;              // 1028 words: conflict-free pad
    extern __shared__ unsigned smem_u[];
    unsigned* WsU = smem_u;                  // [32][1028] tf32 bits
    unsigned* HsU = WsU + 32*LDW;            // [16][1028] tf32 bits
    float*    Gs  = (float*)(HsU + 16*LDW);  // [2][16][32] fp32 gate partials

    const int tid  = threadIdx.x, lane = tid & 31, w = tid >> 5;
    const int u0   = blockIdx.x * 8;
    const int gate = w & 3, half = w >> 2;
    const int g    = lane >> 2, t4 = lane & 3;

    // Load W_hh slice once: rows {gate*1024 + u0 + j}, convert to tf32
    #pragma unroll 4
    for (int j=0;j<32;j++){
        int idx = tid + 256*j;
        int r = idx >> 8, c4 = idx & 255;
        int grow = (r>>3)*HN + u0 + (r&7);
        float4 v = *(const float4*)(W_hh + (size_t)grow*HN + c4*4);
        unsigned* d = WsU + r*LDW + c4*4;
        d[0]=f2tf(v.x); d[1]=f2tf(v.y); d[2]=f2tf(v.z); d[3]=f2tf(v.w);
    }

    for (int t=0; t<SEQ; t++){
        // ---- XG prefetch (independent of h; hides DRAM latency behind barrier)
        float xgi=0.f, xgf=0.f, xgg=0.f, xgo=0.f;
        int bb=0, uu=0;
        if (tid < 128){
            bb = tid >> 3; uu = tid & 7;
            size_t xb = ((size_t)bb*SEQ + t)*G4 + u0 + uu;
            xgi = __ldg(&g_XG[xb]);
            xgf = __ldg(&g_XG[xb + HN]);
            xgg = __ldg(&g_XG[xb + 2*HN]);
            xgo = __ldg(&g_XG[xb + 3*HN]);
        }

        // ---- grid barrier: release flag, acquire all 128 flags
        __syncthreads();                      // prior step's writes ordered
        if (tid == 0){
            __threadfence();
            asm volatile("st.release.gpu.global.u32 [%0], %1;"
                         :: "l"(g_flags + blockIdx.x), "r"((unsigned)(t+1)) : "memory");
        }
        if (tid < 128){
            unsigned v;
            do {
                asm volatile("ld.acquire.gpu.global.u32 %0, [%1];"
                             : "=r"(v) : "l"(g_flags + tid) : "memory");
            } while (v < (unsigned)(t+1));
        }
        __syncthreads();
        __threadfence();

        // ---- copy h(t-1) bits -> smem (no cvt needed)
        const unsigned* hsrc = g_Hb[t & 1];
        #pragma unroll 4
        for (int j=0;j<16;j++){
            int idx = tid + 256*j;
            int r = idx >> 8, c4 = idx & 255;
            *(uint4*)(HsU + r*LDW + c4*4) = *(const uint4*)(hsrc + r*HN + c4*4);
        }
        __syncthreads();

        // ---- gates partial over this warp's K-half (LDS.128 + dual accums)
        float acc0[4] = {0.f,0.f,0.f,0.f};
        float acc1[4] = {0.f,0.f,0.f,0.f};
        {
            const int ks = half * (HN/2);
            const unsigned* hrow0 = HsU + g*LDW       + ks + t4*8;
            const unsigned* hrow1 = HsU + (g+8)*LDW   + ks + t4*8;
            const unsigned* wrow  = WsU + (gate*8+g)*LDW + ks + t4*8;
            #pragma unroll 4
            for (int blk=0; blk<16; blk++){
                const int base = blk*32;
                uint4 a0  = *(const uint4*)(hrow0 + base);
                uint4 a0h = *(const uint4*)(hrow0 + base + 4);
                uint4 a1  = *(const uint4*)(hrow1 + base);
                uint4 a1h = *(const uint4*)(hrow1 + base + 4);
                uint4 b0  = *(const uint4*)(wrow  + base);
                uint4 b0h = *(const uint4*)(wrow  + base + 4);
                MMA_TF32(acc0, a0.x,  a1.x,  a0.y,  a1.y,  b0.x,  b0.y);
                MMA_TF32(acc1, a0.z,  a1.z,  a0.w,  a1.w,  b0.z,  b0.w);
                MMA_TF32(acc0, a0h.x, a1h.x, a0h.y, a1h.y, b0h.x, b0h.y);
                MMA_TF32(acc1, a0h.z, a1h.z, a0h.w, a1h.w, b0h.z, b0h.w);
            }
        }
        float* Gw = Gs + half*(16*32);
        Gw[g*32     + gate*8 + 2*t4    ] = acc0[0] + acc1[0];
        Gw[g*32     + gate*8 + 2*t4 + 1] = acc0[1] + acc1[1];
        Gw[(g+8)*32 + gate*8 + 2*t4    ] = acc0[2] + acc1[2];
        Gw[(g+8)*32 + gate*8 + 2*t4 + 1] = acc0[3] + acc1[3];
        __syncthreads();

        // ---- fused cell update: 16 batches x 8 units = 128 threads
        if (tid < 128){
            const float* G0 = Gs + bb*32;
            const float* G1 = Gs + 16*32 + bb*32;
            float vi = G0[uu]    + G1[uu]    + xgi;
            float vf = G0[8+uu]  + G1[8+uu]  + xgf;
            float vg = G0[16+uu] + G1[16+uu] + xgg;
            float vo = G0[24+uu] + G1[24+uu] + xgo;
            float iv = 1.f/(1.f + expf(-vi));
            float fv = 1.f/(1.f + expf(-vf));
            float gv = tanhf(vg);
            float ov = 1.f/(1.f + expf(-vo));
            int hi = bb*HN + u0 + uu;
            float cv = fv * g_C[hi] + iv * gv;
            float hv = ov * tanhf(cv);
            g_C[hi] = cv;
            unsigned hb = f2tf(hv);
            g_Hb[(t+1) & 1][hi] = hb;                         // next step's input
            g_HS[((size_t)bb*SEQ + t)*HN + u0 + uu] = hb;     // logits operand
        }
    }
}

// ============================================================================
// Launch
// ============================================================================
extern "C" void kernel_launch(void* const* d_in, const int* in_sizes, int n_in,
                              void* d_out, int out_size)
{
    const int*   tgt  = (const int*)  d_in[0];
    const float* h    = (const float*)d_in[1];
    const float* c    = (const float*)d_in[2];
    const float* emb  = (const float*)d_in[3];
    const float* W_ih = (const float*)d_in[4];
    const float* W_hh = (const float*)d_in[5];
    const float* b_ih = (const float*)d_in[6];
    const float* b_hh = (const float*)d_in[7];
    const float* W_fc = (const float*)d_in[8];
    const float* b_fc = (const float*)d_in[9];
    float* out = (float*)d_out;
    (void)in_sizes; (void)n_in; (void)out_size;

    void *pHb, *pC, *pFlags, *pXG, *pHS, *pAr, *pWihT, *pWfcT;
    cudaGetSymbolAddress(&pHb,   g_Hb);
    cudaGetSymbolAddress(&pC,    g_C);
    cudaGetSymbolAddress(&pFlags,g_flags);
    cudaGetSymbolAddress(&pXG,   g_XG);
    cudaGetSymbolAddress(&pHS,   g_HS);
    cudaGetSymbolAddress(&pAr,   g_Arows);
    cudaGetSymbolAddress(&pWihT, g_Wih_t);
    cudaGetSymbolAddress(&pWfcT, g_Wfc_t);

    cudaMemcpyAsync(pHb, h, BB*HN*sizeof(float), cudaMemcpyDeviceToDevice);
    cudaMemcpyAsync(pC,  c, BB*HN*sizeof(float), cudaMemcpyDeviceToDevice);
    cudaMemsetAsync(pFlags, 0, 128*sizeof(unsigned));

    const int smem_g = 3*2*128*36*4;                      // 110,592 B (3-stage)
    const int smem_r = (32*1028 + 16*1028)*4 + 2*16*32*4; // 201,472 B
    cudaFuncSetAttribute(gemm_tf32,   cudaFuncAttributeMaxDynamicSharedMemorySize, smem_g);
    cudaFuncSetAttribute(lstm_kernel, cudaFuncAttributeMaxDynamicSharedMemorySize, smem_r);

    // 0) conversions
    cvt_tf32_kernel<<<16, 256>>>((const float4*)pHb, (uint4*)pHb, BB*HN/4);   // h0 -> tf32 bits in place
    gather_cvt_kernel<<<MROWS, 128>>>(emb, tgt, (unsigned*)pAr);
    cvt_tf32_kernel<<<1024, 256>>>((const float4*)W_ih, (uint4*)pWihT, G4*EMBD/4);
    cvt_tf32_kernel<<<4096, 256>>>((const float4*)W_fc, (uint4*)pWfcT, VOC*(HN/4));

    // 1) XG = embrows @ W_ih^T + b_ih + b_hh   (M=2048, N=4096, K=512)
    dim3 g1(MROWS/128, G4/128);
    gemm_tf32<<<g1, 256, smem_g>>>((const unsigned*)pAr, (const unsigned*)pWihT,
                                   b_ih, b_hh, (float*)pXG, MROWS, G4, EMBD);

    // 2) 128-step recurrence, persistent (128 CTAs)
    lstm_kernel<<<128, 256, smem_r>>>(W_hh);

    // 3) logits = HS @ W_fc^T + b_fc           (M=2048, N=32000, K=1024)
    dim3 g2(MROWS/128, VOC/128);
    gemm_tf32<<<g2, 256, smem_g>>>((const unsigned*)pHS, (const unsigned*)pWfcT,
                                   b_fc, nullptr, out, MROWS, VOC, HN);
}

// round 8
// speedup vs baseline: 1.3211x; 1.3211x over previous
#include <cuda_runtime.h>
#include <cstdint>
#include <math.h>

// Problem constants
#define HN    1024
#define EMBD  512
#define VOC   32000
#define BB    16
#define SEQ   128
#define MROWS (BB*SEQ)   // 2048
#define G4    (4*HN)     // 4096

// Scratch (device globals: allocation-free)
__device__ float    g_XG[MROWS * G4];            // [2048,4096] fp32 gate projections
__device__ unsigned g_HS[MROWS * HN];            // [2048,1024] hidden states (tf32 bits)
__device__ unsigned g_Arows[MROWS * EMBD];       // gathered emb rows as tf32 bits
__device__ unsigned g_Wih_t[G4 * EMBD];          // W_ih as tf32 bits
__device__ unsigned g_Wfc_t[(size_t)VOC * HN];   // W_fc as tf32 bits
__device__ float    g_H[BB * HN];
__device__ float    g_C[BB * HN];
__device__ unsigned g_bar;

__device__ __forceinline__ unsigned f2tf(float x){
    unsigned u; asm("cvt.rna.tf32.f32 %0, %1;" : "=r"(u) : "f"(x)); return u;
}

#define MMA_TF32(d, a0,a1,a2,a3, b0,b1) \
  asm volatile("mma.sync.aligned.m16n8k8.row.col.f32.tf32.tf32.f32 " \
    "{%0,%1,%2,%3}, {%4,%5,%6,%7}, {%8,%9}, {%0,%1,%2,%3};\n" \
    : "+f"(d[0]), "+f"(d[1]), "+f"(d[2]), "+f"(d[3]) \
    : "r"(a0), "r"(a1), "r"(a2), "r"(a3), "r"(b0), "r"(b1))

#define CP16(dst,src) asm volatile("cp.async.cg.shared.global [%0], [%1], 16;\n" :: "r"(dst), "l"(src))
#define CP_COMMIT()   asm volatile("cp.async.commit_group;\n")
#define CP_WAIT(n)    asm volatile("cp.async.wait_group %0;\n" :: "n"(n))

// ============================================================================
// fp32 -> tf32-bits conversion (grid-stride, float4)
// ============================================================================
__global__ void __launch_bounds__(256) cvt_tf32_kernel(
    const float4* __restrict__ in, uint4* __restrict__ out, int n4)
{
    int i = blockIdx.x * blockDim.x + threadIdx.x;
    int stride = gridDim.x * blockDim.x;
    for (; i < n4; i += stride){
        float4 v = in[i];
        uint4 u; u.x=f2tf(v.x); u.y=f2tf(v.y); u.z=f2tf(v.z); u.w=f2tf(v.w);
        out[i] = u;
    }
}

// Gather-convert embedding rows: out[r] = tf32(emb[tgt[r]])
__global__ void __launch_bounds__(128) gather_cvt_kernel(
    const float* __restrict__ emb, const int* __restrict__ tgt,
    unsigned* __restrict__ out)
{
    int row = blockIdx.x;
    const float4* src = (const float4*)(emb + (size_t)tgt[row] * EMBD);
    uint4* dst = (uint4*)(out + (size_t)row * EMBD);
    int t = threadIdx.x;
    float4 v = src[t];
    uint4 u; u.x=f2tf(v.x); u.y=f2tf(v.y); u.z=f2tf(v.z); u.w=f2tf(v.w);
    dst[t] = u;
}

// ============================================================================
// TF32 GEMM on tf32-bit operands: C[M,N] = A[M,K] @ B[N,K]^T + bias0 (+bias1)
// BM=128, BN=128, BK=32, 128 threads (4 warps), 64x64 warp tiles (2x2 grid):
// fragment smem traffic = A x2 + B x2 = 64KB/iter (vs 96KB with 8 warps),
// balancing the 128 B/cyc crossbar against the tensor-pipe floor.
// LDS.128 fragment loads via free k-permutation: thread t4 consumes k-words
// [t4*8 .. t4*8+7]; A and B agree on the permutation, k-reduction is
// order-invariant, so no layout change is needed (validated in R7).
// 2-stage cp.async pipeline. Grid: x = M tiles (fast) so concurrent CTAs
// share B tiles -> B streamed from DRAM ~once.
// ============================================================================
__global__ void __launch_bounds__(128, 2) gemm_tf32(
    const unsigned* __restrict__ A, const unsigned* __restrict__ B,
    const float* __restrict__ bias0, const float* __restrict__ bias1,
    float* __restrict__ C, int M, int N, int K)
{
    constexpr int BM=128, BN=128, BK=32, LD=36;
    extern __shared__ unsigned smem[];
    unsigned* As = smem;                 // [2][128][36]
    unsigned* Bs = smem + 2*BM*LD;       // [2][128][36]

    const int tid  = threadIdx.x;
    const int lane = tid & 31, w = tid >> 5;
    const int bm0  = blockIdx.x * BM;
    const int bn0  = blockIdx.y * BN;
    const int mb   = (w & 1) * 64;       // 2x2 warp grid, 64x64 warp tile
    const int nb   = (w >> 1) * 64;
    const int g    = lane >> 2, t4 = lane & 3;

    // loader: per stage per tile 1024 uint4; 128 threads x 8 each.
    // row(j) = (tid>>3) + 16*j, col4 = tid&7  -> strided from one base.
    const int r0 = tid >> 3, c4 = tid & 7;
    const unsigned* abase = A + (size_t)(bm0 + r0) * K + c4*4;
    const unsigned* bbase = B + (size_t)(bn0 + r0) * K + c4*4;
    unsigned As_b = (unsigned)__cvta_generic_to_shared(As);
    unsigned Bs_b = (unsigned)__cvta_generic_to_shared(Bs);
    const unsigned d0  = (unsigned)((r0*LD + c4*4) * 4);
    const unsigned stS = BM*LD*4;        // stage stride (bytes)
    const unsigned jS  = 16*LD*4;        // per-j smem stride (bytes)

    float acc[4][8][4];
    #pragma unroll
    for (int i=0;i<4;i++)
        #pragma unroll
        for (int j=0;j<8;j++)
            #pragma unroll
            for (int k=0;k<4;k++) acc[i][j][k]=0.f;

    const int niter = K / BK;
    // prologue: stages 0 and 1
    #pragma unroll
    for (int st=0; st<2; st++){
        #pragma unroll
        for (int j=0;j<8;j++){
            CP16(As_b + d0 + st*stS + j*jS, abase + st*BK + (size_t)j*16*K);
            CP16(Bs_b + d0 + st*stS + j*jS, bbase + st*BK + (size_t)j*16*K);
        }
        CP_COMMIT();
    }
    CP_WAIT(1);
    __syncthreads();

    for (int it=0; it<niter; it++){
        const int s = it & 1;
        const unsigned* As_ = As + s*BM*LD;
        const unsigned* Bs_ = Bs + s*BM*LD;
        #pragma unroll
        for (int kq=0; kq<2; kq++){          // each kq: one uint4/row = 2 MMAs-k
            uint4 a[4][2];
            #pragma unroll
            for (int mt=0; mt<4; mt++){
                const unsigned* p = As_ + (mb + mt*16 + g)*LD + t4*8 + kq*4;
                a[mt][0] = *(const uint4*)p;
                a[mt][1] = *(const uint4*)(p + 8*LD);
            }
            #pragma unroll
            for (int nh=0; nh<2; nh++){      // B in two halves: register relief
                uint4 bq[4];
                #pragma unroll
                for (int q=0;q<4;q++)
                    bq[q] = *(const uint4*)(Bs_ + (nb + (nh*4+q)*8 + g)*LD + t4*8 + kq*4);
                #pragma unroll
                for (int mt=0;mt<4;mt++)
                    #pragma unroll
                    for (int q=0;q<4;q++){
                        MMA_TF32(acc[mt][nh*4+q],
                                 a[mt][0].x, a[mt][1].x, a[mt][0].y, a[mt][1].y,
                                 bq[q].x, bq[q].y);
                        MMA_TF32(acc[mt][nh*4+q],
                                 a[mt][0].z, a[mt][1].z, a[mt][0].w, a[mt][1].w,
                                 bq[q].z, bq[q].w);
                    }
            }
        }
        __syncthreads();
        if (it + 2 < niter){
            const int k0 = (it+2)*BK;
            const unsigned so = (unsigned)s*stS;
            #pragma unroll
            for (int j=0;j<8;j++){
                CP16(As_b + d0 + so + j*jS, abase + k0 + (size_t)j*16*K);
                CP16(Bs_b + d0 + so + j*jS, bbase + k0 + (size_t)j*16*K);
            }
            CP_COMMIT();
            CP_WAIT(1);
        } else {
            CP_WAIT(0);
        }
        __syncthreads();
    }

    // epilogue: bias add + float2 stores
    #pragma unroll
    for (int mt=0; mt<4; mt++){
        int row = bm0 + mb + mt*16 + g;
        #pragma unroll
        for (int nt=0; nt<8; nt++){
            int col = bn0 + nb + nt*8 + 2*t4;
            float b0v = bias0[col], b1v = bias0[col+1];
            if (bias1){ b0v += bias1[col]; b1v += bias1[col+1]; }
            float2 v0 = make_float2(acc[mt][nt][0] + b0v, acc[mt][nt][1] + b1v);
            float2 v1 = make_float2(acc[mt][nt][2] + b0v, acc[mt][nt][3] + b1v);
            *(float2*)(C + (size_t)row*N + col)     = v0;
            *(float2*)(C + (size_t)(row+8)*N + col) = v1;
        }
    }
}

// ============================================================================
// Persistent LSTM recurrence (R5-proven version): 128 CTAs (1/SM), each CTA
// owns 8 hidden units. W_hh slice in smem as TF32 for the whole kernel.
// Monotonic-counter grid barrier (single atomic + single poller per CTA).
// ============================================================================
__global__ void __launch_bounds__(256) lstm_kernel(const float* __restrict__ W_hh)
{
    constexpr int LDW = HN + 4;              // 1028: bank-conflict-free pad
    extern __shared__ float smem_f[];
    float* Ws = smem_f;                      // [32][1028] tf32 bits
    float* Hs = Ws + 32*LDW;                 // [16][1028] tf32 bits
    float* Gs = Hs + 16*LDW;                 // [2][16][32] fp32 gate partials

    const int tid  = threadIdx.x, lane = tid & 31, w = tid >> 5;
    const int u0   = blockIdx.x * 8;
    const int gate = w & 3, half = w >> 2;
    const int g    = lane >> 2, t4 = lane & 3;
    unsigned* WsU = (unsigned*)Ws;
    unsigned* HsU = (unsigned*)Hs;

    #pragma unroll 4
    for (int j=0;j<32;j++){
        int idx = tid + 256*j;
        int r = idx >> 8, c4 = idx & 255;
        int grow = (r>>3)*HN + u0 + (r&7);
        float4 v = *(const float4*)(W_hh + (size_t)grow*HN + c4*4);
        unsigned* d = WsU + r*LDW + c4*4;
        d[0]=f2tf(v.x); d[1]=f2tf(v.y); d[2]=f2tf(v.z); d[3]=f2tf(v.w);
    }

    const unsigned nct = gridDim.x;
    for (int t=0; t<SEQ; t++){
        __threadfence();
        __syncthreads();
        if (tid == 0){
            atomicAdd(&g_bar, 1u);
            unsigned target = nct * (unsigned)(t+1);
            while (*(volatile unsigned*)&g_bar < target) { __nanosleep(64); }
        }
        __syncthreads();
        __threadfence();

        #pragma unroll 4
        for (int j=0;j<16;j++){
            int idx = tid + 256*j;
            int r = idx >> 8, c4 = idx & 255;
            float4 v = *(const float4*)(g_H + r*HN + c4*4);
            unsigned* d = HsU + r*LDW + c4*4;
            d[0]=f2tf(v.x); d[1]=f2tf(v.y); d[2]=f2tf(v.z); d[3]=f2tf(v.w);
        }
        __syncthreads();

        float acc0[4] = {0.f,0.f,0.f,0.f};
        float acc1[4] = {0.f,0.f,0.f,0.f};
        {
            const int ks = half * (HN/2);
            const unsigned* pa0 = HsU + g*LDW      + t4 + ks;
            const unsigned* pa1 = HsU + (g+8)*LDW  + t4 + ks;
            const unsigned* pb  = WsU + (gate*8 + g)*LDW + t4 + ks;
            #pragma unroll 4
            for (int k=0; k<HN/2; k+=16){
                {
                    unsigned a0=pa0[k], a2=pa0[k+4], a1=pa1[k], a3=pa1[k+4];
                    unsigned b0=pb[k],  b1=pb[k+4];
                    MMA_TF32(acc0, a0,a1,a2,a3, b0,b1);
                }
                {
                    unsigned a0=pa0[k+8], a2=pa0[k+12], a1=pa1[k+8], a3=pa1[k+12];
                    unsigned b0=pb[k+8],  b1=pb[k+12];
                    MMA_TF32(acc1, a0,a1,a2,a3, b0,b1);
                }
            }
        }
        float* Gw = Gs + half*(16*32);
        Gw[g*32     + gate*8 + 2*t4    ] = acc0[0] + acc1[0];
        Gw[g*32     + gate*8 + 2*t4 + 1] = acc0[1] + acc1[1];
        Gw[(g+8)*32 + gate*8 + 2*t4    ] = acc0[2] + acc1[2];
        Gw[(g+8)*32 + gate*8 + 2*t4 + 1] = acc0[3] + acc1[3];
        __syncthreads();

        if (tid < 128){
            int b = tid >> 3, uu = tid & 7;
            const float* G0 = Gs + b*32;
            const float* G1 = Gs + 16*32 + b*32;
            size_t xb = ((size_t)b*SEQ + t)*G4 + u0 + uu;
            float vi = G0[uu]    + G1[uu]    + g_XG[xb];
            float vf = G0[8+uu]  + G1[8+uu]  + g_XG[xb + HN];
            float vg = G0[16+uu] + G1[16+uu] + g_XG[xb + 2*HN];
            float vo = G0[24+uu] + G1[24+uu] + g_XG[xb + 3*HN];
            float iv = 1.f/(1.f + expf(-vi));
            float fv = 1.f/(1.f + expf(-vf));
            float gv = tanhf(vg);
            float ov = 1.f/(1.f + expf(-vo));
            int hi = b*HN + u0 + uu;
            float cv = fv * g_C[hi] + iv * gv;
            float hv = ov * tanhf(cv);
            g_C[hi] = cv;
            g_H[hi] = hv;
            g_HS[((size_t)b*SEQ + t)*HN + u0 + uu] = f2tf(hv);
        }
    }
}

// ============================================================================
// Launch
// ============================================================================
extern "C" void kernel_launch(void* const* d_in, const int* in_sizes, int n_in,
                              void* d_out, int out_size)
{
    const int*   tgt  = (const int*)  d_in[0];
    const float* h    = (const float*)d_in[1];
    const float* c    = (const float*)d_in[2];
    const float* emb  = (const float*)d_in[3];
    const float* W_ih = (const float*)d_in[4];
    const float* W_hh = (const float*)d_in[5];
    const float* b_ih = (const float*)d_in[6];
    const float* b_hh = (const float*)d_in[7];
    const float* W_fc = (const float*)d_in[8];
    const float* b_fc = (const float*)d_in[9];
    float* out = (float*)d_out;
    (void)in_sizes; (void)n_in; (void)out_size;

    void *pH, *pC, *pbar, *pXG, *pHS, *pAr, *pWihT, *pWfcT;
    cudaGetSymbolAddress(&pH,    g_H);
    cudaGetSymbolAddress(&pC,    g_C);
    cudaGetSymbolAddress(&pbar,  g_bar);
    cudaGetSymbolAddress(&pXG,   g_XG);
    cudaGetSymbolAddress(&pHS,   g_HS);
    cudaGetSymbolAddress(&pAr,   g_Arows);
    cudaGetSymbolAddress(&pWihT, g_Wih_t);
    cudaGetSymbolAddress(&pWfcT, g_Wfc_t);

    cudaMemcpyAsync(pH, h, BB*HN*sizeof(float), cudaMemcpyDeviceToDevice);
    cudaMemcpyAsync(pC, c, BB*HN*sizeof(float), cudaMemcpyDeviceToDevice);
    cudaMemsetAsync(pbar, 0, sizeof(unsigned));

    const int smem_g = 2*128*36*4 * 2;                    // 73,728 B (2-stage)
    const int smem_r = (32*1028 + 16*1028)*4 + 2*16*32*4; // 201,472 B
    cudaFuncSetAttribute(gemm_tf32,   cudaFuncAttributeMaxDynamicSharedMemorySize, smem_g);
    cudaFuncSetAttribute(lstm_kernel, cudaFuncAttributeMaxDynamicSharedMemorySize, smem_r);

    // 0) conversions
    gather_cvt_kernel<<<MROWS, 128>>>(emb, tgt, (unsigned*)pAr);
    cvt_tf32_kernel<<<1024, 256>>>((const float4*)W_ih, (uint4*)pWihT, G4*EMBD/4);
    cvt_tf32_kernel<<<4096, 256>>>((const float4*)W_fc, (uint4*)pWfcT, VOC*(HN/4));

    // 1) XG = embrows @ W_ih^T + b_ih + b_hh   (M=2048, N=4096, K=512)
    dim3 g1(MROWS/128, G4/128);
    gemm_tf32<<<g1, 128, smem_g>>>((const unsigned*)pAr, (const unsigned*)pWihT,
                                   b_ih, b_hh, (float*)pXG, MROWS, G4, EMBD);

    // 2) 128-step recurrence, persistent (128 CTAs)
    lstm_kernel<<<128, 256, smem_r>>>(W_hh);

    // 3) logits = HS @ W_fc^T + b_fc           (M=2048, N=32000, K=1024)
    dim3 g2(MROWS/128, VOC/128);
    gemm_tf32<<<g2, 128, smem_g>>>((const unsigned*)pHS, (const unsigned*)pWfcT,
                                   b_fc, nullptr, out, MROWS, VOC, HN);
}

// round 9
// speedup vs baseline: 2.1652x; 1.6390x over previous
#include <cuda_runtime.h>
#include <cuda_fp16.h>
#include <cstdint>
#include <math.h>

// Problem constants
#define HN    1024
#define EMBD  512
#define VOC   32000
#define BB    16
#define SEQ   128
#define MROWS (BB*SEQ)   // 2048
#define G4    (4*HN)     // 4096

// Scratch (device globals: allocation-free). fp16 operands stored as packed
// half2 words (unsigned) so GEMM addressing is in 32-bit "words" = 2 halves.
__device__ float    g_XG[MROWS * G4];              // [2048,4096] fp32 gate projections
__device__ unsigned g_HS[MROWS * HN/2];            // hidden states, half2 words
__device__ unsigned g_Arows[MROWS * EMBD/2];       // gathered emb rows, half2 words
__device__ unsigned g_Wih_h[G4 * EMBD/2];          // W_ih, half2 words
__device__ unsigned g_Wfc_h[(size_t)VOC * HN/2];   // W_fc, half2 words
__device__ unsigned g_Hb[2][BB * HN/2];            // h double buffer, half2 words
__device__ float    g_C[BB * HN];
__device__ unsigned g_bar;

__device__ __forceinline__ unsigned f2h2(float a, float b){
    __half2 h = __floats2half2_rn(a, b);
    return *reinterpret_cast<unsigned*>(&h);
}

// m16n8k16 fp16 MMA, fp32 accumulate.
// Slot semantics (k-permutation-free): a0=(row g, word P0), a1=(row g+8, P0),
// a2=(row g, P1), a3=(row g+8, P1); b0=(col g, P0), b1=(col g, P1).
// Each word = 2 consecutive k (half2) — packing identical on A and B.
#define MMA_F16(d, a0,a1,a2,a3, b0,b1) \
  asm volatile("mma.sync.aligned.m16n8k16.row.col.f32.f16.f16.f32 " \
    "{%0,%1,%2,%3}, {%4,%5,%6,%7}, {%8,%9}, {%0,%1,%2,%3};\n" \
    : "+f"(d[0]), "+f"(d[1]), "+f"(d[2]), "+f"(d[3]) \
    : "r"(a0), "r"(a1), "r"(a2), "r"(a3), "r"(b0), "r"(b1))

#define CP16(dst,src) asm volatile("cp.async.cg.shared.global [%0], [%1], 16;\n" :: "r"(dst), "l"(src))
#define CP_COMMIT()   asm volatile("cp.async.commit_group;\n")
#define CP_WAIT(n)    asm volatile("cp.async.wait_group %0;\n" :: "n"(n))

// ============================================================================
// fp32 -> fp16 conversion (grid-stride; float4 in, uint2 = 2 half2 out)
// ============================================================================
__global__ void __launch_bounds__(256) cvt_f16_kernel(
    const float4* __restrict__ in, uint2* __restrict__ out, int n4)
{
    int i = blockIdx.x * blockDim.x + threadIdx.x;
    int stride = gridDim.x * blockDim.x;
    for (; i < n4; i += stride){
        float4 v = in[i];
        uint2 u; u.x = f2h2(v.x, v.y); u.y = f2h2(v.z, v.w);
        out[i] = u;
    }
}

// Gather-convert embedding rows: out[r] = fp16(emb[tgt[r]])
__global__ void __launch_bounds__(128) gather_cvt_kernel(
    const float* __restrict__ emb, const int* __restrict__ tgt,
    unsigned* __restrict__ out)
{
    int row = blockIdx.x;
    const float4* src = (const float4*)(emb + (size_t)tgt[row] * EMBD);
    uint2* dst = (uint2*)(out + (size_t)row * (EMBD/2));
    int t = threadIdx.x;                      // 128 threads, 128 float4
    float4 v = src[t];
    uint2 u; u.x = f2h2(v.x, v.y); u.y = f2h2(v.z, v.w);
    dst[t] = u;
}

// ============================================================================
// FP16 GEMM: C[M,N] = A[M,K] @ B[N,K]^T + bias0 (+bias1), fp32 accumulate.
// Operands are half2-packed words; Kw = K/2 words. BM=BN=128, BKW=32 words
// (64 halves per iter), 256 threads (8 warps, 32x64 warp tiles), 2-stage
// cp.async pipeline. LDS.128 fragment loads: thread t4 owns words
// [t4*8 .. t4*8+7] of each 32-word K-chunk (conflict-free with LD=36;
// k-reduction order-invariant, A/B agree). Grid: x = M tiles (fast) so
// concurrent CTAs share B tiles -> B streamed from DRAM ~once.
// ============================================================================
__global__ void __launch_bounds__(256) gemm_f16(
    const unsigned* __restrict__ A, const unsigned* __restrict__ B,
    const float* __restrict__ bias0, const float* __restrict__ bias1,
    float* __restrict__ C, int M, int N, int Kw)
{
    constexpr int BM=128, BN=128, BKW=32, LD=36;
    extern __shared__ unsigned smem[];
    unsigned* As = smem;                 // [2][128][36]
    unsigned* Bs = smem + 2*BM*LD;       // [2][128][36]

    const int tid  = threadIdx.x;
    const int lane = tid & 31, w = tid >> 5;
    const int bm0  = blockIdx.x * BM;
    const int bn0  = blockIdx.y * BN;
    const int mb   = (w & 3) * 32;       // warp M offset (4x2 warp grid)
    const int nb   = (w >> 2) * 64;      // warp N offset
    const int g    = lane >> 2, t4 = lane & 3;

    // loader: 1024 uint4 per stage per tile, 256 threads x 4
    const unsigned* asrc[4]; unsigned adst[4];
    const unsigned* bsrc[4]; unsigned bdst[4];
    unsigned As_b = (unsigned)__cvta_generic_to_shared(As);
    unsigned Bs_b = (unsigned)__cvta_generic_to_shared(Bs);
    #pragma unroll
    for (int j=0;j<4;j++){
        int idx = tid + 256*j;
        int r = idx >> 3, c4 = idx & 7;
        asrc[j] = A + (size_t)(bm0 + r) * Kw + c4*4;
        adst[j] = As_b + (unsigned)((r*LD + c4*4) * 4);
        bsrc[j] = B + (size_t)(bn0 + r) * Kw + c4*4;
        bdst[j] = Bs_b + (unsigned)((r*LD + c4*4) * 4);
    }
    const unsigned stS = BM*LD*4;        // stage stride bytes

    float acc[2][8][4];
    #pragma unroll
    for (int i=0;i<2;i++)
        #pragma unroll
        for (int j=0;j<8;j++)
            #pragma unroll
            for (int k=0;k<4;k++) acc[i][j][k]=0.f;

    const int niter = Kw / BKW;
    #pragma unroll
    for (int j=0;j<4;j++){ CP16(adst[j], asrc[j]); CP16(bdst[j], bsrc[j]); }
    CP_COMMIT();
    #pragma unroll
    for (int j=0;j<4;j++){ CP16(adst[j]+stS, asrc[j]+BKW); CP16(bdst[j]+stS, bsrc[j]+BKW); }
    CP_COMMIT();
    CP_WAIT(1);
    __syncthreads();

    for (int it=0; it<niter; it++){
        const int s = it & 1;
        const unsigned* As_ = As + s*BM*LD;
        const unsigned* Bs_ = Bs + s*BM*LD;
        #pragma unroll
        for (int kq=0; kq<2; kq++){      // per kq: one uint4/row = 2 MMAs (k32)
            uint4 a[2][2], b[8];
            #pragma unroll
            for (int mt=0; mt<2; mt++){
                const unsigned* p = As_ + (mb + mt*16 + g)*LD + t4*8 + kq*4;
                a[mt][0] = *(const uint4*)p;
                a[mt][1] = *(const uint4*)(p + 8*LD);
            }
            #pragma unroll
            for (int nt=0; nt<8; nt++)
                b[nt] = *(const uint4*)(Bs_ + (nb + nt*8 + g)*LD + t4*8 + kq*4);
            #pragma unroll
            for (int mt=0; mt<2; mt++)
                #pragma unroll
                for (int nt=0; nt<8; nt++){
                    MMA_F16(acc[mt][nt], a[mt][0].x, a[mt][1].x, a[mt][0].y, a[mt][1].y,
                            b[nt].x, b[nt].y);
                    MMA_F16(acc[mt][nt], a[mt][0].z, a[mt][1].z, a[mt][0].w, a[mt][1].w,
                            b[nt].z, b[nt].w);
                }
        }
        __syncthreads();
        if (it + 2 < niter){
            const int k0 = (it+2)*BKW;
            const unsigned so = (unsigned)s*stS;
            #pragma unroll
            for (int j=0;j<4;j++){ CP16(adst[j]+so, asrc[j]+k0); CP16(bdst[j]+so, bsrc[j]+k0); }
            CP_COMMIT();
            CP_WAIT(1);
        } else {
            CP_WAIT(0);
        }
        __syncthreads();
    }

    // epilogue: bias add + float2 stores
    #pragma unroll
    for (int mt=0; mt<2; mt++){
        int row = bm0 + mb + mt*16 + g;
        #pragma unroll
        for (int nt=0; nt<8; nt++){
            int col = bn0 + nb + nt*8 + 2*t4;
            float b0v = bias0[col], b1v = bias0[col+1];
            if (bias1){ b0v += bias1[col]; b1v += bias1[col+1]; }
            float2 v0 = make_float2(acc[mt][nt][0] + b0v, acc[mt][nt][1] + b1v);
            float2 v1 = make_float2(acc[mt][nt][2] + b0v, acc[mt][nt][3] + b1v);
            *(float2*)(C + (size_t)row*N + col)     = v0;
            *(float2*)(C + (size_t)(row+8)*N + col) = v1;
        }
    }
}

// ============================================================================
// Persistent LSTM recurrence: 128 CTAs (1/SM), each CTA owns 8 hidden units.
// W_hh slice (32 gate rows x 1024) converted to fp16 in smem once.
// Per step: grid barrier (R5-proven monotonic atomic) -> copy h bits -> 8
// warps do m16n8k16 fp16 MMA (split-K x2, dual accumulators) -> fused cell
// update. h double-buffered as half2 words (race-free, no per-step cvt).
// ============================================================================
__global__ void __launch_bounds__(256) lstm_kernel(const float* __restrict__ W_hh)
{
    constexpr int HW  = HN/2;            // 512 words per row
    constexpr int LDW = HW + 4;          // 516: row stride mod 32 = 4 -> frag
                                         // banks {4g+8*t4} all distinct
    extern __shared__ unsigned smem_u[];
    unsigned* WsU = smem_u;              // [32][516] half2 words
    unsigned* HsU = WsU + 32*LDW;        // [16][516] half2 words
    float*    Gs  = (float*)(HsU + 16*LDW);  // [2][16][32] fp32 gate partials

    const int tid  = threadIdx.x, lane = tid & 31, w = tid >> 5;
    const int u0   = blockIdx.x * 8;
    const int gate = w & 3, half = w >> 2;
    const int g    = lane >> 2, t4 = lane & 3;

    // Load W_hh slice once, convert fp32 -> half2 words.
    // 32 rows x 256 float4 = 8192 float4; 256 threads x 32.
    #pragma unroll 4
    for (int j=0;j<32;j++){
        int idx = tid + 256*j;
        int r = idx >> 8, c4 = idx & 255;
        int grow = (r>>3)*HN + u0 + (r&7);
        float4 v = *(const float4*)(W_hh + (size_t)grow*HN + c4*4);
        uint2 u; u.x = f2h2(v.x, v.y); u.y = f2h2(v.z, v.w);
        *(uint2*)(WsU + r*LDW + c4*2) = u;
    }

    const unsigned nct = gridDim.x;
    for (int t=0; t<SEQ; t++){
        // ---- grid barrier (monotonic counter; reset by memset each launch)
        __threadfence();
        __syncthreads();
        if (tid == 0){
            atomicAdd(&g_bar, 1u);
            unsigned target = nct * (unsigned)(t+1);
            while (*(volatile unsigned*)&g_bar < target) { __nanosleep(64); }
        }
        __syncthreads();
        __threadfence();

        // ---- copy h(t-1) half2 words -> smem (16 rows x 128 uint4)
        const unsigned* hsrc = g_Hb[t & 1];
        #pragma unroll 4
        for (int j=0;j<8;j++){
            int idx = tid + 256*j;
            int r = idx >> 7, c = idx & 127;
            *(uint4*)(HsU + r*LDW + c*4) = *(const uint4*)(hsrc + r*HW + c*4);
        }
        __syncthreads();

        // ---- gates partial over this warp's K-half (256 words = 512 halves)
        float acc0[4] = {0.f,0.f,0.f,0.f};
        float acc1[4] = {0.f,0.f,0.f,0.f};
        {
            const int ksw = half * (HW/2);
            const unsigned* hrow0 = HsU + g*LDW          + ksw + t4*8;
            const unsigned* hrow1 = HsU + (g+8)*LDW      + ksw + t4*8;
            const unsigned* wrow  = WsU + (gate*8+g)*LDW + ksw + t4*8;
            #pragma unroll 4
            for (int j=0; j<8; j++){         // 8 groups x 32 words
                const int base = j*32;
                uint4 a0  = *(const uint4*)(hrow0 + base);
                uint4 a0h = *(const uint4*)(hrow0 + base + 4);
                uint4 a1  = *(const uint4*)(hrow1 + base);
                uint4 a1h = *(const uint4*)(hrow1 + base + 4);
                uint4 b0  = *(const uint4*)(wrow  + base);
                uint4 b0h = *(const uint4*)(wrow  + base + 4);
                MMA_F16(acc0, a0.x,  a1.x,  a0.y,  a1.y,  b0.x,  b0.y);
                MMA_F16(acc1, a0.z,  a1.z,  a0.w,  a1.w,  b0.z,  b0.w);
                MMA_F16(acc0, a0h.x, a1h.x, a0h.y, a1h.y, b0h.x, b0h.y);
                MMA_F16(acc1, a0h.z, a1h.z, a0h.w, a1h.w, b0h.z, b0h.w);
            }
        }
        float* Gw = Gs + half*(16*32);
        Gw[g*32     + gate*8 + 2*t4    ] = acc0[0] + acc1[0];
        Gw[g*32     + gate*8 + 2*t4 + 1] = acc0[1] + acc1[1];
        Gw[(g+8)*32 + gate*8 + 2*t4    ] = acc0[2] + acc1[2];
        Gw[(g+8)*32 + gate*8 + 2*t4 + 1] = acc0[3] + acc1[3];
        __syncthreads();

        // ---- fused cell update: 16 batches x 8 units = 128 threads
        if (tid < 128){
            int b = tid >> 3, uu = tid & 7;
            const float* G0 = Gs + b*32;
            const float* G1 = Gs + 16*32 + b*32;
            size_t xb = ((size_t)b*SEQ + t)*G4 + u0 + uu;
            float vi = G0[uu]    + G1[uu]    + g_XG[xb];
            float vf = G0[8+uu]  + G1[8+uu]  + g_XG[xb + HN];
            float vg = G0[16+uu] + G1[16+uu] + g_XG[xb + 2*HN];
            float vo = G0[24+uu] + G1[24+uu] + g_XG[xb + 3*HN];
            float iv = 1.f/(1.f + expf(-vi));
            float fv = 1.f/(1.f + expf(-vf));
            float gv = tanhf(vg);
            float ov = 1.f/(1.f + expf(-vo));
            int hi = b*HN + u0 + uu;
            float cv = fv * g_C[hi] + iv * gv;
            float hv = ov * tanhf(cv);
            g_C[hi] = cv;
            __half hh = __float2half_rn(hv);
            ((__half*)g_Hb[(t+1) & 1])[hi] = hh;                      // next step
            ((__half*)g_HS)[((size_t)b*SEQ + t)*HN + u0 + uu] = hh;   // logits A
        }
        // next iteration's barrier orders these global writes vs. reads
    }
}

// ============================================================================
// Launch
// ============================================================================
extern "C" void kernel_launch(void* const* d_in, const int* in_sizes, int n_in,
                              void* d_out, int out_size)
{
    const int*   tgt  = (const int*)  d_in[0];
    const float* h    = (const float*)d_in[1];
    const float* c    = (const float*)d_in[2];
    const float* emb  = (const float*)d_in[3];
    const float* W_ih = (const float*)d_in[4];
    const float* W_hh = (const float*)d_in[5];
    const float* b_ih = (const float*)d_in[6];
    const float* b_hh = (const float*)d_in[7];
    const float* W_fc = (const float*)d_in[8];
    const float* b_fc = (const float*)d_in[9];
    float* out = (float*)d_out;
    (void)in_sizes; (void)n_in; (void)out_size;

    void *pHb, *pC, *pbar, *pXG, *pHS, *pAr, *pWih, *pWfc;
    cudaGetSymbolAddress(&pHb,  g_Hb);
    cudaGetSymbolAddress(&pC,   g_C);
    cudaGetSymbolAddress(&pbar, g_bar);
    cudaGetSymbolAddress(&pXG,  g_XG);
    cudaGetSymbolAddress(&pHS,  g_HS);
    cudaGetSymbolAddress(&pAr,  g_Arows);
    cudaGetSymbolAddress(&pWih, g_Wih_h);
    cudaGetSymbolAddress(&pWfc, g_Wfc_h);

    cudaMemcpyAsync(pC, c, BB*HN*sizeof(float), cudaMemcpyDeviceToDevice);
    cudaMemsetAsync(pbar, 0, sizeof(unsigned));

    const int smem_g = 2*128*36*4 * 2;                         // 73,728 B
    const int smem_r = (32*516 + 16*516)*4 + 2*16*32*4;        // 103,168 B
    cudaFuncSetAttribute(gemm_f16,    cudaFuncAttributeMaxDynamicSharedMemorySize, smem_g);
    cudaFuncSetAttribute(lstm_kernel, cudaFuncAttributeMaxDynamicSharedMemorySize, smem_r);

    // 0) conversions (fp32 -> fp16)
    cvt_f16_kernel<<<16, 256>>>((const float4*)h, (uint2*)pHb, BB*HN/4);  // h0 -> g_Hb[0]
    gather_cvt_kernel<<<MROWS, 128>>>(emb, tgt, (unsigned*)pAr);
    cvt_f16_kernel<<<1024, 256>>>((const float4*)W_ih, (uint2*)pWih, G4*EMBD/4);
    cvt_f16_kernel<<<4096, 256>>>((const float4*)W_fc, (uint2*)pWfc, VOC*(HN/4));

    // 1) XG = embrows @ W_ih^T + b_ih + b_hh   (M=2048, N=4096, Kw=256)
    dim3 g1(MROWS/128, G4/128);
    gemm_f16<<<g1, 256, smem_g>>>((const unsigned*)pAr, (const unsigned*)pWih,
                                  b_ih, b_hh, (float*)pXG, MROWS, G4, EMBD/2);

    // 2) 128-step recurrence, persistent (128 CTAs)
    lstm_kernel<<<128, 256, smem_r>>>(W_hh);

    // 3) logits = HS @ W_fc^T + b_fc           (M=2048, N=32000, Kw=512)
    dim3 g2(MROWS/128, VOC/128);
    gemm_f16<<<g2, 256, smem_g>>>((const unsigned*)pHS, (const unsigned*)pWfc,
                                  b_fc, nullptr, out, MROWS, VOC, HN/2);
}

// round 10
// speedup vs baseline: 2.2326x; 1.0311x over previous
#include <cuda_runtime.h>
#include <cuda_fp16.h>
#include <cstdint>
#include <math.h>

// Problem constants
#define HN    1024
#define EMBD  512
#define VOC   32000
#define BB    16
#define SEQ   128
#define MROWS (BB*SEQ)   // 2048
#define G4    (4*HN)     // 4096

// Scratch (device globals: allocation-free). fp16 operands stored as packed
// half2 words (unsigned) so GEMM addressing is in 32-bit "words" = 2 halves.
__device__ float    g_XG[MROWS * G4];              // [2048,4096] fp32 gate projections
__device__ unsigned g_HS[MROWS * HN/2];            // hidden states, half2 words
__device__ unsigned g_Arows[MROWS * EMBD/2];       // gathered emb rows, half2 words
__device__ unsigned g_Wih_h[G4 * EMBD/2];          // W_ih, half2 words
__device__ unsigned g_Wfc_h[(size_t)VOC * HN/2];   // W_fc, half2 words
__device__ unsigned g_Hb[2][BB * HN/2];            // h double buffer, half2 words
__device__ float    g_C[BB * HN];
// Hierarchical barrier: 8 counters, 2KB apart -> distinct L2 lines/partitions
#define NCTR 8
#define CTR_STRIDE 512                              // 512 uints = 2048 B
__device__ unsigned g_ctrs[NCTR * CTR_STRIDE];

__device__ __forceinline__ unsigned f2h2(float a, float b){
    __half2 h = __floats2half2_rn(a, b);
    return *reinterpret_cast<unsigned*>(&h);
}

// m16n8k16 fp16 MMA, fp32 accumulate.
// Slot semantics: a0=(row g, word P0), a1=(row g+8, P0), a2=(row g, P1),
// a3=(row g+8, P1); b0=(col g, P0), b1=(col g, P1). Each word = 2 consecutive
// k (half2) — packing identical on A and B; k-order free (validated R9).
#define MMA_F16(d, a0,a1,a2,a3, b0,b1) \
  asm volatile("mma.sync.aligned.m16n8k16.row.col.f32.f16.f16.f32 " \
    "{%0,%1,%2,%3}, {%4,%5,%6,%7}, {%8,%9}, {%0,%1,%2,%3};\n" \
    : "+f"(d[0]), "+f"(d[1]), "+f"(d[2]), "+f"(d[3]) \
    : "r"(a0), "r"(a1), "r"(a2), "r"(a3), "r"(b0), "r"(b1))

#define CP16(dst,src) asm volatile("cp.async.cg.shared.global [%0], [%1], 16;\n" :: "r"(dst), "l"(src))
#define CP_COMMIT()   asm volatile("cp.async.commit_group;\n")
#define CP_WAIT(n)    asm volatile("cp.async.wait_group %0;\n" :: "n"(n))

// ============================================================================
// fp32 -> fp16 conversion (grid-stride; float4 in, uint2 = 2 half2 out)
// ============================================================================
__global__ void __launch_bounds__(256) cvt_f16_kernel(
    const float4* __restrict__ in, uint2* __restrict__ out, int n4)
{
    int i = blockIdx.x * blockDim.x + threadIdx.x;
    int stride = gridDim.x * blockDim.x;
    for (; i < n4; i += stride){
        float4 v = in[i];
        uint2 u; u.x = f2h2(v.x, v.y); u.y = f2h2(v.z, v.w);
        out[i] = u;
    }
}

// Gather-convert embedding rows: out[r] = fp16(emb[tgt[r]])
__global__ void __launch_bounds__(128) gather_cvt_kernel(
    const float* __restrict__ emb, const int* __restrict__ tgt,
    unsigned* __restrict__ out)
{
    int row = blockIdx.x;
    const float4* src = (const float4*)(emb + (size_t)tgt[row] * EMBD);
    uint2* dst = (uint2*)(out + (size_t)row * (EMBD/2));
    int t = threadIdx.x;                      // 128 threads, 128 float4
    float4 v = src[t];
    uint2 u; u.x = f2h2(v.x, v.y); u.y = f2h2(v.z, v.w);
    dst[t] = u;
}

// ============================================================================
// FP16 GEMM (frozen from R9): C[M,N] = A[M,K] @ B[N,K]^T + bias0 (+bias1),
// fp32 accumulate. Operands half2-packed; Kw = K/2 words. BM=BN=128, BKW=32,
// 256 threads (8 warps, 32x64 warp tiles), 2-stage cp.async, LDS.128
// fragment loads via free k-permutation. Grid: x = M tiles (fast).
// ============================================================================
__global__ void __launch_bounds__(256) gemm_f16(
    const unsigned* __restrict__ A, const unsigned* __restrict__ B,
    const float* __restrict__ bias0, const float* __restrict__ bias1,
    float* __restrict__ C, int M, int N, int Kw)
{
    constexpr int BM=128, BN=128, BKW=32, LD=36;
    extern __shared__ unsigned smem[];
    unsigned* As = smem;                 // [2][128][36]
    unsigned* Bs = smem + 2*BM*LD;       // [2][128][36]

    const int tid  = threadIdx.x;
    const int lane = tid & 31, w = tid >> 5;
    const int bm0  = blockIdx.x * BM;
    const int bn0  = blockIdx.y * BN;
    const int mb   = (w & 3) * 32;       // warp M offset (4x2 warp grid)
    const int nb   = (w >> 2) * 64;      // warp N offset
    const int g    = lane >> 2, t4 = lane & 3;

    const unsigned* asrc[4]; unsigned adst[4];
    const unsigned* bsrc[4]; unsigned bdst[4];
    unsigned As_b = (unsigned)__cvta_generic_to_shared(As);
    unsigned Bs_b = (unsigned)__cvta_generic_to_shared(Bs);
    #pragma unroll
    for (int j=0;j<4;j++){
        int idx = tid + 256*j;
        int r = idx >> 3, c4 = idx & 7;
        asrc[j] = A + (size_t)(bm0 + r) * Kw + c4*4;
        adst[j] = As_b + (unsigned)((r*LD + c4*4) * 4);
        bsrc[j] = B + (size_t)(bn0 + r) * Kw + c4*4;
        bdst[j] = Bs_b + (unsigned)((r*LD + c4*4) * 4);
    }
    const unsigned stS = BM*LD*4;

    float acc[2][8][4];
    #pragma unroll
    for (int i=0;i<2;i++)
        #pragma unroll
        for (int j=0;j<8;j++)
            #pragma unroll
            for (int k=0;k<4;k++) acc[i][j][k]=0.f;

    const int niter = Kw / BKW;
    #pragma unroll
    for (int j=0;j<4;j++){ CP16(adst[j], asrc[j]); CP16(bdst[j], bsrc[j]); }
    CP_COMMIT();
    #pragma unroll
    for (int j=0;j<4;j++){ CP16(adst[j]+stS, asrc[j]+BKW); CP16(bdst[j]+stS, bsrc[j]+BKW); }
    CP_COMMIT();
    CP_WAIT(1);
    __syncthreads();

    for (int it=0; it<niter; it++){
        const int s = it & 1;
        const unsigned* As_ = As + s*BM*LD;
        const unsigned* Bs_ = Bs + s*BM*LD;
        #pragma unroll
        for (int kq=0; kq<2; kq++){
            uint4 a[2][2], b[8];
            #pragma unroll
            for (int mt=0; mt<2; mt++){
                const unsigned* p = As_ + (mb + mt*16 + g)*LD + t4*8 + kq*4;
                a[mt][0] = *(const uint4*)p;
                a[mt][1] = *(const uint4*)(p + 8*LD);
            }
            #pragma unroll
            for (int nt=0; nt<8; nt++)
                b[nt] = *(const uint4*)(Bs_ + (nb + nt*8 + g)*LD + t4*8 + kq*4);
            #pragma unroll
            for (int mt=0; mt<2; mt++)
                #pragma unroll
                for (int nt=0; nt<8; nt++){
                    MMA_F16(acc[mt][nt], a[mt][0].x, a[mt][1].x, a[mt][0].y, a[mt][1].y,
                            b[nt].x, b[nt].y);
                    MMA_F16(acc[mt][nt], a[mt][0].z, a[mt][1].z, a[mt][0].w, a[mt][1].w,
                            b[nt].z, b[nt].w);
                }
        }
        __syncthreads();
        if (it + 2 < niter){
            const int k0 = (it+2)*BKW;
            const unsigned so = (unsigned)s*stS;
            #pragma unroll
            for (int j=0;j<4;j++){ CP16(adst[j]+so, asrc[j]+k0); CP16(bdst[j]+so, bsrc[j]+k0); }
            CP_COMMIT();
            CP_WAIT(1);
        } else {
            CP_WAIT(0);
        }
        __syncthreads();
    }

    #pragma unroll
    for (int mt=0; mt<2; mt++){
        int row = bm0 + mb + mt*16 + g;
        #pragma unroll
        for (int nt=0; nt<8; nt++){
            int col = bn0 + nb + nt*8 + 2*t4;
            float b0v = bias0[col], b1v = bias0[col+1];
            if (bias1){ b0v += bias1[col]; b1v += bias1[col+1]; }
            float2 v0 = make_float2(acc[mt][nt][0] + b0v, acc[mt][nt][1] + b1v);
            float2 v1 = make_float2(acc[mt][nt][2] + b0v, acc[mt][nt][3] + b1v);
            *(float2*)(C + (size_t)row*N + col)     = v0;
            *(float2*)(C + (size_t)(row+8)*N + col) = v1;
        }
    }
}

// ============================================================================
// Persistent LSTM recurrence: 128 CTAs (1/SM), each CTA owns 8 hidden units.
// Hierarchical 8-counter grid barrier: CTA (cta&7) arrives at counter (cta&7)
// (16 arrivals/counter, parallel across 8 L2 lines 2KB apart); 8 threads/CTA
// poll (one counter each). XG prefetched before the barrier.
// h double-buffered as half2 words; fp16 m16n8k16 MMA.
// ============================================================================
__global__ void __launch_bounds__(256) lstm_kernel(const float* __restrict__ W_hh)
{
    constexpr int HW  = HN/2;            // 512 words per row
    constexpr int LDW = HW + 4;          // 516: conflict-free frag banks
    extern __shared__ unsigned smem_u[];
    unsigned* WsU = smem_u;              // [32][516] half2 words
    unsigned* HsU = WsU + 32*LDW;        // [16][516] half2 words
    float*    Gs  = (float*)(HsU + 16*LDW);  // [2][16][32] fp32 gate partials

    const int tid  = threadIdx.x, lane = tid & 31, w = tid >> 5;
    const int u0   = blockIdx.x * 8;
    const int gate = w & 3, half = w >> 2;
    const int g    = lane >> 2, t4 = lane & 3;

    // Load W_hh slice once, convert fp32 -> half2 words.
    #pragma unroll 4
    for (int j=0;j<32;j++){
        int idx = tid + 256*j;
        int r = idx >> 8, c4 = idx & 255;
        int grow = (r>>3)*HN + u0 + (r&7);
        float4 v = *(const float4*)(W_hh + (size_t)grow*HN + c4*4);
        uint2 u; u.x = f2h2(v.x, v.y); u.y = f2h2(v.z, v.w);
        *(uint2*)(WsU + r*LDW + c4*2) = u;
    }

    for (int t=0; t<SEQ; t++){
        // ---- XG prefetch (independent of h; hides load latency behind barrier)
        float xgi=0.f, xgf=0.f, xgg=0.f, xgo=0.f;
        int bb=0, uu=0;
        if (tid < 128){
            bb = tid >> 3; uu = tid & 7;
            size_t xb = ((size_t)bb*SEQ + t)*G4 + u0 + uu;
            xgi = __ldg(&g_XG[xb]);
            xgf = __ldg(&g_XG[xb + HN]);
            xgg = __ldg(&g_XG[xb + 2*HN]);
            xgo = __ldg(&g_XG[xb + 3*HN]);
        }

        // ---- hierarchical grid barrier
        __syncthreads();                              // prior-step writes done
        if (tid == 0){
            __threadfence();
            atomicAdd(&g_ctrs[(blockIdx.x & (NCTR-1)) * CTR_STRIDE], 1u);
        }
        if (tid < NCTR){
            const unsigned target = (128u/NCTR) * (unsigned)(t+1);
            unsigned v;
            for (;;){
                asm volatile("ld.acquire.gpu.global.u32 %0, [%1];"
                             : "=r"(v) : "l"(g_ctrs + tid*CTR_STRIDE) : "memory");
                if (v >= target) break;
                __nanosleep(32);
            }
        }
        __syncthreads();

        // ---- copy h(t-1) half2 words -> smem (16 rows x 128 uint4)
        const unsigned* hsrc = g_Hb[t & 1];
        #pragma unroll 4
        for (int j=0;j<8;j++){
            int idx = tid + 256*j;
            int r = idx >> 7, c = idx & 127;
            *(uint4*)(HsU + r*LDW + c*4) = *(const uint4*)(hsrc + r*HW + c*4);
        }
        __syncthreads();

        // ---- gates partial over this warp's K-half (256 words = 512 halves)
        float acc0[4] = {0.f,0.f,0.f,0.f};
        float acc1[4] = {0.f,0.f,0.f,0.f};
        {
            const int ksw = half * (HW/2);
            const unsigned* hrow0 = HsU + g*LDW          + ksw + t4*8;
            const unsigned* hrow1 = HsU + (g+8)*LDW      + ksw + t4*8;
            const unsigned* wrow  = WsU + (gate*8+g)*LDW + ksw + t4*8;
            #pragma unroll 4
            for (int j=0; j<8; j++){
                const int base = j*32;
                uint4 a0  = *(const uint4*)(hrow0 + base);
                uint4 a0h = *(const uint4*)(hrow0 + base + 4);
                uint4 a1  = *(const uint4*)(hrow1 + base);
                uint4 a1h = *(const uint4*)(hrow1 + base + 4);
                uint4 b0  = *(const uint4*)(wrow  + base);
                uint4 b0h = *(const uint4*)(wrow  + base + 4);
                MMA_F16(acc0, a0.x,  a1.x,  a0.y,  a1.y,  b0.x,  b0.y);
                MMA_F16(acc1, a0.z,  a1.z,  a0.w,  a1.w,  b0.z,  b0.w);
                MMA_F16(acc0, a0h.x, a1h.x, a0h.y, a1h.y, b0h.x, b0h.y);
                MMA_F16(acc1, a0h.z, a1h.z, a0h.w, a1h.w, b0h.z, b0h.w);
            }
        }
        float* Gw = Gs + half*(16*32);
        Gw[g*32     + gate*8 + 2*t4    ] = acc0[0] + acc1[0];
        Gw[g*32     + gate*8 + 2*t4 + 1] = acc0[1] + acc1[1];
        Gw[(g+8)*32 + gate*8 + 2*t4    ] = acc0[2] + acc1[2];
        Gw[(g+8)*32 + gate*8 + 2*t4 + 1] = acc0[3] + acc1[3];
        __syncthreads();

        // ---- fused cell update: 16 batches x 8 units = 128 threads
        if (tid < 128){
            const float* G0 = Gs + bb*32;
            const float* G1 = Gs + 16*32 + bb*32;
            float vi = G0[uu]    + G1[uu]    + xgi;
            float vf = G0[8+uu]  + G1[8+uu]  + xgf;
            float vg = G0[16+uu] + G1[16+uu] + xgg;
            float vo = G0[24+uu] + G1[24+uu] + xgo;
            float iv = 1.f/(1.f + expf(-vi));
            float fv = 1.f/(1.f + expf(-vf));
            float gv = tanhf(vg);
            float ov = 1.f/(1.f + expf(-vo));
            int hi = bb*HN + u0 + uu;
            float cv = fv * g_C[hi] + iv * gv;
            float hv = ov * tanhf(cv);
            g_C[hi] = cv;
            __half hh = __float2half_rn(hv);
            ((__half*)g_Hb[(t+1) & 1])[hi] = hh;                      // next step
            ((__half*)g_HS)[((size_t)bb*SEQ + t)*HN + u0 + uu] = hh;  // logits A
        }
        // next iteration's barrier (fence + acquire) orders these writes
    }
}

// ============================================================================
// Launch
// ============================================================================
extern "C" void kernel_launch(void* const* d_in, const int* in_sizes, int n_in,
                              void* d_out, int out_size)
{
    const int*   tgt  = (const int*)  d_in[0];
    const float* h    = (const float*)d_in[1];
    const float* c    = (const float*)d_in[2];
    const float* emb  = (const float*)d_in[3];
    const float* W_ih = (const float*)d_in[4];
    const float* W_hh = (const float*)d_in[5];
    const float* b_ih = (const float*)d_in[6];
    const float* b_hh = (const float*)d_in[7];
    const float* W_fc = (const float*)d_in[8];
    const float* b_fc = (const float*)d_in[9];
    float* out = (float*)d_out;
    (void)in_sizes; (void)n_in; (void)out_size;

    void *pHb, *pC, *pCtrs, *pXG, *pHS, *pAr, *pWih, *pWfc;
    cudaGetSymbolAddress(&pHb,   g_Hb);
    cudaGetSymbolAddress(&pC,    g_C);
    cudaGetSymbolAddress(&pCtrs, g_ctrs);
    cudaGetSymbolAddress(&pXG,   g_XG);
    cudaGetSymbolAddress(&pHS,   g_HS);
    cudaGetSymbolAddress(&pAr,   g_Arows);
    cudaGetSymbolAddress(&pWih,  g_Wih_h);
    cudaGetSymbolAddress(&pWfc,  g_Wfc_h);

    cudaMemcpyAsync(pC, c, BB*HN*sizeof(float), cudaMemcpyDeviceToDevice);
    cudaMemsetAsync(pCtrs, 0, NCTR*CTR_STRIDE*sizeof(unsigned));

    const int smem_g = 2*128*36*4 * 2;                         // 73,728 B
    const int smem_r = (32*516 + 16*516)*4 + 2*16*32*4;        // 103,168 B
    cudaFuncSetAttribute(gemm_f16,    cudaFuncAttributeMaxDynamicSharedMemorySize, smem_g);
    cudaFuncSetAttribute(lstm_kernel, cudaFuncAttributeMaxDynamicSharedMemorySize, smem_r);

    // 0) conversions (fp32 -> fp16)
    cvt_f16_kernel<<<16, 256>>>((const float4*)h, (uint2*)pHb, BB*HN/4);  // h0 -> g_Hb[0]
    gather_cvt_kernel<<<MROWS, 128>>>(emb, tgt, (unsigned*)pAr);
    cvt_f16_kernel<<<1024, 256>>>((const float4*)W_ih, (uint2*)pWih, G4*EMBD/4);
    cvt_f16_kernel<<<4096, 256>>>((const float4*)W_fc, (uint2*)pWfc, VOC*(HN/4));

    // 1) XG = embrows @ W_ih^T + b_ih + b_hh   (M=2048, N=4096, Kw=256)
    dim3 g1(MROWS/128, G4/128);
    gemm_f16<<<g1, 256, smem_g>>>((const unsigned*)pAr, (const unsigned*)pWih,
                                  b_ih, b_hh, (float*)pXG, MROWS, G4, EMBD/2);

    // 2) 128-step recurrence, persistent (128 CTAs)
    lstm_kernel<<<128, 256, smem_r>>>(W_hh);

    // 3) logits = HS @ W_fc^T + b_fc           (M=2048, N=32000, Kw=512)
    dim3 g2(MROWS/128, VOC/128);
    gemm_f16<<<g2, 256, smem_g>>>((const unsigned*)pHS, (const unsigned*)pWfc,
                                  b_fc, nullptr, out, MROWS, VOC, HN/2);
}